// round 6
// baseline (speedup 1.0000x reference)
#include <cuda_runtime.h>
#include <cuda_fp16.h>
#include <cstdint>

// ---------------------------------------------------------------------------
// DiGCN on GB300 — R6.
//  * GEMM: 512 threads/CTA, 4m x 12n per-thread tile, <=128 regs
//    -> 4 warps/SMSP (was 2). Same block tile / smem / FMA work.
//  * conv64 v4: 8 lanes/edge uint4 gathers, 4 edge-groups per warp,
//    coalesced edge preload + shfl broadcast.
// ---------------------------------------------------------------------------

#define N_NODES   200000
#define N_EDGES   3200000
#define NPG       50000
#define NGRAPH    4
#define HID       64

__device__ float  g_y0[(size_t)N_NODES * HID];
__device__ __half g_y1h[(size_t)N_NODES * HID];
__device__ __half g_y2h[(size_t)N_NODES * HID];
__device__ float  g_x [(size_t)N_NODES * HID];

__device__ int   g_deg[2 * N_NODES];
__device__ int   g_rs [2 * N_NODES + 1];
__device__ int   g_bsum[256];
__device__ int2  g_e  [2 * N_EDGES];

__device__ float g_s0[N_NODES];
__device__ float g_s1[N_NODES];
__device__ float g_s2[N_NODES];
__device__ float g_x3[N_NODES];

// ---------------- helpers ----------------------------------------------------
__device__ __forceinline__ void fma2(unsigned long long &d,
                                     unsigned long long a,
                                     unsigned long long b) {
    asm("fma.rn.f32x2 %0, %1, %2, %0;" : "+l"(d) : "l"(a), "l"(b));
}
__device__ __forceinline__ unsigned long long rep2(float x) {
    unsigned long long r;
    unsigned u = __float_as_uint(x);
    asm("mov.b64 %0, {%1, %1};" : "=l"(r) : "r"(u));
    return r;
}

// ---------------- CSR build (concatenated) ------------------------------------
__global__ void k_zero(int* __restrict__ p, int n) {
    int i = blockIdx.x * blockDim.x + threadIdx.x;
    if (i < n) p[i] = 0;
}

__global__ void k_hist2(const int* __restrict__ dst1, const int* __restrict__ dst2,
                        int* __restrict__ deg, int E) {
    int e = blockIdx.x * blockDim.x + threadIdx.x;
    if (e < E)          atomicAdd(&deg[__ldcs(&dst1[e])], 1);
    else if (e < 2 * E) atomicAdd(&deg[N_NODES + __ldcs(&dst2[e - E])], 1);
}

__global__ void k_scan_sums(const int* __restrict__ deg, int* __restrict__ bsum, int n) {
    __shared__ int sh[16];
    int tid = threadIdx.x;
    int base = blockIdx.x * 2048 + tid * 4;
    int s = 0;
#pragma unroll
    for (int c = 0; c < 4; ++c) if (base + c < n) s += deg[base + c];
#pragma unroll
    for (int o = 16; o; o >>= 1) s += __shfl_xor_sync(0xffffffffu, s, o);
    if ((tid & 31) == 0) sh[tid >> 5] = s;
    __syncthreads();
    if (tid < 16) {
        int v = sh[tid];
#pragma unroll
        for (int o = 8; o; o >>= 1) v += __shfl_xor_sync(0x0000ffffu, v, o);
        if (tid == 0) bsum[blockIdx.x] = v;
    }
}

__global__ void k_scan_bsum(int* __restrict__ bsum, int nb) {
    __shared__ int ws[8];
    int tid = threadIdx.x;
    int lane = tid & 31, w = tid >> 5;
    int orig = (tid < nb) ? bsum[tid] : 0;
    int v = orig;
#pragma unroll
    for (int o = 1; o < 32; o <<= 1) {
        int t = __shfl_up_sync(0xffffffffu, v, o);
        if (lane >= o) v += t;
    }
    if (lane == 31) ws[w] = v;
    __syncthreads();
    if (tid == 0) { int a = 0; for (int i = 0; i < 8; ++i) { int t = ws[i]; ws[i] = a; a += t; } }
    __syncthreads();
    v += ws[w];
    if (tid < nb) bsum[tid] = v - orig;
}

__global__ void k_scan_write(int* __restrict__ deg, const int* __restrict__ bsum,
                             int* __restrict__ rs, int n, int total) {
    __shared__ int wsum[16];
    int tid = threadIdx.x;
    int lane = tid & 31, wid = tid >> 5;
    int base = blockIdx.x * 2048 + tid * 4;
    int v[4]; int s = 0;
#pragma unroll
    for (int c = 0; c < 4; ++c) { v[c] = (base + c < n) ? deg[base + c] : 0; s += v[c]; }
    int si = s;
#pragma unroll
    for (int o = 1; o < 32; o <<= 1) {
        int t = __shfl_up_sync(0xffffffffu, si, o);
        if (lane >= o) si += t;
    }
    if (lane == 31) wsum[wid] = si;
    __syncthreads();
    if (tid < 16) {
        int t = wsum[tid];
#pragma unroll
        for (int o = 1; o < 16; o <<= 1) {
            int u = __shfl_up_sync(0x0000ffffu, t, o);
            if (tid >= o) t += u;
        }
        wsum[tid] = t;
    }
    __syncthreads();
    int bbase = (wid == 0) ? 0 : wsum[wid - 1];
    int off = bsum[blockIdx.x] + bbase + (si - s);
#pragma unroll
    for (int c = 0; c < 4; ++c) {
        if (base + c < n) { rs[base + c] = off; deg[base + c] = off; off += v[c]; }
    }
    if (blockIdx.x == 0 && tid == 0) rs[n] = total;
}

__global__ void k_fill2(const int* __restrict__ src1, const int* __restrict__ dst1,
                        const float* __restrict__ w1,
                        const int* __restrict__ src2, const int* __restrict__ dst2,
                        const float* __restrict__ w2,
                        int* __restrict__ cur, int2* __restrict__ out, int E) {
    int e = blockIdx.x * blockDim.x + threadIdx.x;
    int s, slot; float w;
    if (e < E) {
        slot = __ldcs(&dst1[e]); s = __ldcs(&src1[e]); w = __ldcs(&w1[e]);
    } else if (e < 2 * E) {
        int e2 = e - E;
        slot = N_NODES + __ldcs(&dst2[e2]); s = __ldcs(&src2[e2]); w = __ldcs(&w2[e2]);
    } else return;
    int pos = atomicAdd(&cur[slot], 1);
    out[pos] = make_int2(s, __float_as_int(w));
}

// ---------------- GEMM: [M x K] @ [K x 192], 512 thr, 4m x 12n tile ----------
template <int K>
__global__ void __launch_bounds__(512, 1)
k_gemm(const float* __restrict__ X,
       const float* __restrict__ W0, const float* __restrict__ W1, const float* __restrict__ W2,
       const float* __restrict__ B0, const float* __restrict__ B1, const float* __restrict__ B2,
       float* __restrict__ Y0, __half* __restrict__ Y1h, __half* __restrict__ Y2h, int M)
{
    extern __shared__ float smem[];
    float* Xst = smem;              // [K][128]  (k-major, m contiguous)
    float* Ws  = smem + K * 128;    // [K][192]
    float* cb  = Ws + K * 192;      // [64]

    const int tid = threadIdx.x;
    const int r0  = blockIdx.x * 128;

    if (tid < 64) cb[tid] = B0[tid] + B1[tid] + B2[tid];

    // X tile: K*32 float4, 512 threads
#pragma unroll
    for (int p = 0; p < K / 16; ++p) {
        int idx = p * 512 + tid;
        int row = idx & 127;
        int kc  = idx >> 7;
        float4 v = make_float4(0.f, 0.f, 0.f, 0.f);
        int grow = r0 + row;
        if (grow < M) v = __ldcs(reinterpret_cast<const float4*>(&X[(size_t)grow * K + kc * 4]));
        Xst[(kc * 4 + 0) * 128 + row] = v.x;
        Xst[(kc * 4 + 1) * 128 + row] = v.y;
        Xst[(kc * 4 + 2) * 128 + row] = v.z;
        Xst[(kc * 4 + 3) * 128 + row] = v.w;
    }
    // W tile: K*48 float4, 512 threads
#pragma unroll
    for (int p = 0; p < (K * 48) / 512; ++p) {
        int idx = p * 512 + tid;
        int j4 = idx % 48, k = idx / 48;
        int j = j4 * 4;
        const float* Wm = (j < 64) ? W0 : ((j < 128) ? W1 : W2);
        int jj = j & 63;
        float4 v = *reinterpret_cast<const float4*>(&Wm[k * 64 + jj]);
        *reinterpret_cast<float4*>(&Ws[k * 192 + j]) = v;
    }
    __syncthreads();

    const int tx = tid & 15, ty = tid >> 4;   // ty 0..31
    const int mb = ty * 4, nb = tx * 12;

    unsigned long long acc[4][6];
#pragma unroll
    for (int i = 0; i < 4; ++i)
#pragma unroll
        for (int j = 0; j < 6; ++j) acc[i][j] = 0ull;

    const unsigned long long* Wsu = reinterpret_cast<const unsigned long long*>(Ws);

#pragma unroll 4
    for (int k = 0; k < K; ++k) {
        float4 a0 = *reinterpret_cast<const float4*>(&Xst[k * 128 + mb]);
        const unsigned long long* bp = &Wsu[k * 96 + tx * 6];
        unsigned long long b0 = bp[0], b1 = bp[1], b2 = bp[2],
                           b3 = bp[3], b4 = bp[4], b5 = bp[5];
        unsigned long long ar[4];
        ar[0] = rep2(a0.x); ar[1] = rep2(a0.y); ar[2] = rep2(a0.z); ar[3] = rep2(a0.w);
#pragma unroll
        for (int i = 0; i < 4; ++i) {
            fma2(acc[i][0], ar[i], b0);
            fma2(acc[i][1], ar[i], b1);
            fma2(acc[i][2], ar[i], b2);
            fma2(acc[i][3], ar[i], b3);
            fma2(acc[i][4], ar[i], b4);
            fma2(acc[i][5], ar[i], b5);
        }
    }

#pragma unroll
    for (int i = 0; i < 4; ++i) {
        int row = r0 + mb + i;
        if (row >= M) continue;
#pragma unroll
        for (int j = 0; j < 6; ++j) {
            float f0 = __uint_as_float((unsigned)acc[i][j]);
            float f1 = __uint_as_float((unsigned)(acc[i][j] >> 32));
            int col = nb + 2 * j;
            if (col < 64) {
                float2 o = make_float2(f0 + cb[col], f1 + cb[col + 1]);
                __stcs(reinterpret_cast<float2*>(&Y0[(size_t)row * 64 + col]), o);
            } else if (col < 128) {
                *reinterpret_cast<__half2*>(&Y1h[(size_t)row * 64 + col - 64]) =
                    __floats2half2_rn(f0, f1);
            } else {
                *reinterpret_cast<__half2*>(&Y2h[(size_t)row * 64 + col - 128]) =
                    __floats2half2_rn(f0, f1);
            }
        }
    }
}

// ---------------- conv64 v4: 8 lanes/edge uint4, 4 edge-groups per warp ------
__device__ __forceinline__ void conv_seg4(const __half* __restrict__ yt,
                                          const int2* __restrict__ ee,
                                          int p0, int pe, int g, int c,
                                          int lane, float acc[8])
{
    for (int p = p0; p < pe; p += 32) {
        int nblk = pe - p; if (nblk > 32) nblk = 32;
        int pl = lane < nblk ? lane : nblk - 1;
        int2 e = __ldcs(&ee[p + pl]);
#pragma unroll 4
        for (int j = 0; j < 32; j += 4) {
            if (j >= nblk) break;
            int k = j + g;
            int sel = k < nblk ? k : 0;
            int   s = __shfl_sync(0xffffffffu, e.x, sel);
            float w = __int_as_float(__shfl_sync(0xffffffffu, e.y, sel));
            if (k >= nblk) w = 0.f;
            uint4 h = __ldg(reinterpret_cast<const uint4*>(
                           yt + ((size_t)s << 6) + (c << 3)));
            float2 f;
            f = __half22float2(*reinterpret_cast<__half2*>(&h.x));
            acc[0] = fmaf(w, f.x, acc[0]); acc[1] = fmaf(w, f.y, acc[1]);
            f = __half22float2(*reinterpret_cast<__half2*>(&h.y));
            acc[2] = fmaf(w, f.x, acc[2]); acc[3] = fmaf(w, f.y, acc[3]);
            f = __half22float2(*reinterpret_cast<__half2*>(&h.z));
            acc[4] = fmaf(w, f.x, acc[4]); acc[5] = fmaf(w, f.y, acc[5]);
            f = __half22float2(*reinterpret_cast<__half2*>(&h.w));
            acc[6] = fmaf(w, f.x, acc[6]); acc[7] = fmaf(w, f.y, acc[7]);
        }
    }
}

__global__ void k_conv64(const float* __restrict__ y0,
                         const __half* __restrict__ y1, const __half* __restrict__ y2,
                         const int* __restrict__ rs, const int2* __restrict__ ee,
                         float* __restrict__ xout, int M)
{
    int n = (blockIdx.x * blockDim.x + threadIdx.x) >> 5;
    if (n >= M) return;
    int lane = threadIdx.x & 31;
    int g = lane >> 3;        // edge group 0..3
    int c = lane & 7;         // 16B chunk within 128B row

    float acc[8];
#pragma unroll
    for (int i = 0; i < 8; ++i) acc[i] = 0.f;

    conv_seg4(y1, ee, __ldg(&rs[n]),            __ldg(&rs[n + 1]),            g, c, lane, acc);
    conv_seg4(y2, ee, __ldg(&rs[N_NODES + n]),  __ldg(&rs[N_NODES + n + 1]),  g, c, lane, acc);

#pragma unroll
    for (int i = 0; i < 8; ++i) {
        acc[i] += __shfl_xor_sync(0xffffffffu, acc[i], 8);
        acc[i] += __shfl_xor_sync(0xffffffffu, acc[i], 16);
    }
    if (g == 0) {
        const float4* yp = reinterpret_cast<const float4*>(&y0[(size_t)n * 64 + c * 8]);
        float4 a = __ldcs(yp), b = __ldcs(yp + 1);
        a.x += acc[0]; a.y += acc[1]; a.z += acc[2]; a.w += acc[3];
        b.x += acc[4]; b.y += acc[5]; b.z += acc[6]; b.w += acc[7];
        float4* op = reinterpret_cast<float4*>(&xout[(size_t)n * 64 + c * 8]);
        __stcs(op, a); __stcs(op + 1, b);
    }
}

// ---------------- block3 GEMM (64 -> 3 scalars): warp per node ---------------
__global__ void k_gemm3(const float* __restrict__ X,
                        const float* __restrict__ w0, const float* __restrict__ w1,
                        const float* __restrict__ w2,
                        const float* __restrict__ b0, const float* __restrict__ b1,
                        const float* __restrict__ b2,
                        float* __restrict__ s0, float* __restrict__ s1,
                        float* __restrict__ s2, int M)
{
    __shared__ float ws[3][64];
    int tid = threadIdx.x;
    if (tid < 64) { ws[0][tid] = w0[tid]; ws[1][tid] = w1[tid]; ws[2][tid] = w2[tid]; }
    __syncthreads();
    int n = blockIdx.x * (blockDim.x >> 5) + (tid >> 5);
    if (n >= M) return;
    int lane = tid & 31;
    float2 xv = __ldcs(reinterpret_cast<const float2*>(&X[(size_t)n * 64 + lane * 2]));
    float p0 = xv.x * ws[0][2 * lane] + xv.y * ws[0][2 * lane + 1];
    float p1 = xv.x * ws[1][2 * lane] + xv.y * ws[1][2 * lane + 1];
    float p2 = xv.x * ws[2][2 * lane] + xv.y * ws[2][2 * lane + 1];
#pragma unroll
    for (int o = 16; o; o >>= 1) {
        p0 += __shfl_xor_sync(0xffffffffu, p0, o);
        p1 += __shfl_xor_sync(0xffffffffu, p1, o);
        p2 += __shfl_xor_sync(0xffffffffu, p2, o);
    }
    if (lane == 0) {
        s0[n] = p0 + (b0[0] + b1[0] + b2[0]);
        s1[n] = p1;
        s2[n] = p2;
    }
}

// ---------------- block3 conv: warp per node ---------------------------------
__global__ void k_conv1(const float* __restrict__ s0, const float* __restrict__ s1,
                        const float* __restrict__ s2,
                        const int* __restrict__ rs, const int2* __restrict__ ee,
                        float* __restrict__ x3, int M)
{
    int n = (blockIdx.x * blockDim.x + threadIdx.x) >> 5;
    if (n >= M) return;
    int lane = threadIdx.x & 31;
    float acc = 0.f;
    for (int p = __ldg(&rs[n]) + lane, pe = __ldg(&rs[n + 1]); p < pe; p += 32) {
        int2 a = __ldcs(&ee[p]);
        acc = fmaf(__int_as_float(a.y), __ldg(&s1[a.x]), acc);
    }
    for (int p = __ldg(&rs[N_NODES + n]) + lane, pe = __ldg(&rs[N_NODES + n + 1]); p < pe; p += 32) {
        int2 a = __ldcs(&ee[p]);
        acc = fmaf(__int_as_float(a.y), __ldg(&s2[a.x]), acc);
    }
#pragma unroll
    for (int o = 16; o; o >>= 1) acc += __shfl_xor_sync(0xffffffffu, acc, o);
    if (lane == 0) x3[n] = s0[n] + acc;
}

// ---------------- readout + output copy --------------------------------------
__global__ void k_readout(const float* __restrict__ x3, float* __restrict__ out,
                          int out_size)
{
    __shared__ float sh[256];
    int g = blockIdx.x;
    float m = -3.402823466e38f;
    for (int i = threadIdx.x; i < NPG; i += blockDim.x)
        m = fmaxf(m, x3[g * NPG + i]);
    sh[threadIdx.x] = m;
    __syncthreads();
    for (int s = 128; s; s >>= 1) {
        if (threadIdx.x < s) sh[threadIdx.x] = fmaxf(sh[threadIdx.x], sh[threadIdx.x + s]);
        __syncthreads();
    }
    if (threadIdx.x == 0 && g < out_size) out[g] = sh[0];
}

__global__ void k_copy_out(const float* __restrict__ x3, float* __restrict__ out,
                           int out_size)
{
    int i = blockIdx.x * blockDim.x + threadIdx.x;
    if (i >= N_NODES) return;
    float v = __ldg(&x3[i]);
    if (4 + i < out_size)            __stcs(&out[4 + i], v);
    if (4 + N_NODES + i < out_size)  __stcs(&out[4 + N_NODES + i], v);
}

// ---------------------------------------------------------------------------
extern "C" void kernel_launch(void* const* d_in, const int* in_sizes, int n_in,
                              void* d_out, int out_size)
{
    const int E = N_EDGES, NN = N_NODES;

    const float* x   = (const float*)d_in[0];
    const int*   ei1 = (const int*)  d_in[1];
    const float* ew1 = (const float*)d_in[2];
    const int*   ei2 = (const int*)  d_in[3];
    const float* ew2 = (const float*)d_in[4];
    int base = (in_sizes[5] == 1) ? 6 : 5;
    const float* W[3][3]; const float* B[3][3];
    for (int blk = 0; blk < 3; ++blk)
        for (int part = 0; part < 3; ++part) {
            W[blk][part] = (const float*)d_in[base + blk * 6 + part * 2];
            B[blk][part] = (const float*)d_in[base + blk * 6 + part * 2 + 1];
        }

    float *y0, *gx, *s0, *s1, *s2, *x3;
    __half *y1h, *y2h;
    int *deg, *rs, *bs;
    int2 *ee;
    cudaGetSymbolAddress((void**)&y0, g_y0);
    cudaGetSymbolAddress((void**)&y1h, g_y1h);
    cudaGetSymbolAddress((void**)&y2h, g_y2h);
    cudaGetSymbolAddress((void**)&gx, g_x);
    cudaGetSymbolAddress((void**)&s0, g_s0);
    cudaGetSymbolAddress((void**)&s1, g_s1);
    cudaGetSymbolAddress((void**)&s2, g_s2);
    cudaGetSymbolAddress((void**)&x3, g_x3);
    cudaGetSymbolAddress((void**)&deg, g_deg);
    cudaGetSymbolAddress((void**)&rs, g_rs);
    cudaGetSymbolAddress((void**)&bs, g_bsum);
    cudaGetSymbolAddress((void**)&ee, g_e);

    static cudaStream_t sA = nullptr;
    static cudaEvent_t evRoot, evA, evX3, evCopy;
    if (!sA) {
        cudaStreamCreateWithFlags(&sA, cudaStreamNonBlocking);
        cudaEventCreateWithFlags(&evRoot, cudaEventDisableTiming);
        cudaEventCreateWithFlags(&evA,    cudaEventDisableTiming);
        cudaEventCreateWithFlags(&evX3,   cudaEventDisableTiming);
        cudaEventCreateWithFlags(&evCopy, cudaEventDisableTiming);
    }

    const int smem128 = (128 * 128 + 128 * 192 + 64) * 4;
    const int smem64  = (64 * 128 + 64 * 192 + 64) * 4;
    cudaFuncSetAttribute(k_gemm<128>, cudaFuncAttributeMaxDynamicSharedMemorySize, smem128);
    cudaFuncSetAttribute(k_gemm<64>,  cudaFuncAttributeMaxDynamicSharedMemorySize, smem64);

    const int N2  = 2 * NN;
    const int SB  = (N2 + 2047) / 2048;
    const int EG2 = (2 * E + 255) / 256;
    const int NG2 = (N2 + 255) / 256;
    const int NG  = (NN + 255) / 256;
    const int GG  = (NN + 127) / 128;
    const int CG  = (NN * 32 + 255) / 256;

    // fork
    cudaEventRecord(evRoot, 0);
    cudaStreamWaitEvent(sA, evRoot, 0);

    k_zero<<<NG2, 256, 0, sA>>>(deg, N2);
    k_hist2<<<EG2, 256, 0, sA>>>(ei1 + E, ei2 + E, deg, E);
    k_scan_sums<<<SB, 512, 0, sA>>>(deg, bs, N2);
    // enqueue idx 3: GEMM1 (the slot ncu captures)
    k_gemm<128><<<GG, 512, smem128>>>(x, W[0][0], W[0][1], W[0][2],
                                      B[0][0], B[0][1], B[0][2],
                                      y0, y1h, y2h, NN);
    k_scan_bsum<<<1, 256, 0, sA>>>(bs, SB);
    k_scan_write<<<SB, 512, 0, sA>>>(deg, bs, rs, N2, 2 * E);
    k_fill2<<<EG2, 256, 0, sA>>>(ei1, ei1 + E, ew1, ei2, ei2 + E, ew2, deg, ee, E);
    cudaEventRecord(evA, sA);

    // join
    cudaStreamWaitEvent(0, evA, 0);

    k_conv64<<<CG, 256>>>(y0, y1h, y2h, rs, ee, gx, NN);

    k_gemm<64><<<GG, 512, smem64>>>(gx, W[1][0], W[1][1], W[1][2],
                                    B[1][0], B[1][1], B[1][2],
                                    y0, y1h, y2h, NN);
    k_conv64<<<CG, 256>>>(y0, y1h, y2h, rs, ee, gx, NN);

    k_gemm3<<<CG, 256>>>(gx, W[2][0], W[2][1], W[2][2],
                         B[2][0], B[2][1], B[2][2], s0, s1, s2, NN);
    k_conv1<<<CG, 256>>>(s0, s1, s2, rs, ee, x3, NN);

    cudaEventRecord(evX3, 0);
    cudaStreamWaitEvent(sA, evX3, 0);
    k_copy_out<<<NG, 256, 0, sA>>>(x3, (float*)d_out, out_size);
    cudaEventRecord(evCopy, sA);

    k_readout<<<NGRAPH, 256>>>(x3, (float*)d_out, out_size);
    cudaStreamWaitEvent(0, evCopy, 0);
}

// round 8
// speedup vs baseline: 1.5914x; 1.5914x over previous
#include <cuda_runtime.h>
#include <cuda_fp16.h>
#include <cstdint>

// ---------------------------------------------------------------------------
// DiGCN on GB300 — R8.
//  * Big GEMMs on tensor cores via mma.sync.m16n8k16 (fp16 in, fp32 acc) —
//    baseline PTX that survives the harness's compute_103 PTX target
//    (tcgen05 does not: 'a'-suffix feature, falsified in R7).
//  * Block tile 128x192, 512 thr (16 warps 4x4), warp tile 32x48.
//  * Rest: proven R3/R7 scaffolding (concat CSR overlap, fp16 tables).
// ---------------------------------------------------------------------------

#define N_NODES   200000
#define N_EDGES   3200000
#define NPG       50000
#define NGRAPH    4
#define HID       64

__device__ float  g_y0[(size_t)N_NODES * HID];
__device__ __half g_y1h[(size_t)N_NODES * HID];
__device__ __half g_y2h[(size_t)N_NODES * HID];
__device__ float  g_x [(size_t)N_NODES * HID];

__device__ __half g_wb1h[192 * 128];   // block1 W^T fp16 [n][k]
__device__ __half g_wb2h[192 * 64];    // block2 W^T fp16 [n][k]

__device__ int   g_deg[2 * N_NODES];
__device__ int   g_rs [2 * N_NODES + 1];
__device__ int   g_bsum[256];
__device__ int2  g_e  [2 * N_EDGES];

__device__ float g_s0[N_NODES];
__device__ float g_s1[N_NODES];
__device__ float g_s2[N_NODES];
__device__ float g_x3[N_NODES];

// ---------------- helpers ------------------------------------------------------
__device__ __forceinline__ uint32_t smem_u32(const void* p) {
    uint32_t a;
    asm("{ .reg .u64 t; cvta.to.shared.u64 t, %1; cvt.u32.u64 %0, t; }"
        : "=r"(a) : "l"(p));
    return a;
}
__device__ __forceinline__ void ldmatrix_x4(uint32_t* r, uint32_t addr) {
    asm volatile("ldmatrix.sync.aligned.m8n8.x4.shared.b16 {%0,%1,%2,%3}, [%4];"
                 : "=r"(r[0]), "=r"(r[1]), "=r"(r[2]), "=r"(r[3]) : "r"(addr));
}
__device__ __forceinline__ void ldmatrix_x2(uint32_t* r, uint32_t addr) {
    asm volatile("ldmatrix.sync.aligned.m8n8.x2.shared.b16 {%0,%1}, [%2];"
                 : "=r"(r[0]), "=r"(r[1]) : "r"(addr));
}
__device__ __forceinline__ void mma16816(float* c, const uint32_t* a, const uint32_t* b) {
    asm volatile(
        "mma.sync.aligned.m16n8k16.row.col.f32.f16.f16.f32 "
        "{%0,%1,%2,%3}, {%4,%5,%6,%7}, {%8,%9}, {%0,%1,%2,%3};"
        : "+f"(c[0]), "+f"(c[1]), "+f"(c[2]), "+f"(c[3])
        : "r"(a[0]), "r"(a[1]), "r"(a[2]), "r"(a[3]), "r"(b[0]), "r"(b[1]));
}

// ---------------- weight prep: fp32 [k][64]x3 -> fp16 [n][k] -----------------
__global__ void k_prepw(const float* __restrict__ w10, const float* __restrict__ w11,
                        const float* __restrict__ w12,
                        const float* __restrict__ w20, const float* __restrict__ w21,
                        const float* __restrict__ w22,
                        __half* __restrict__ wb1, __half* __restrict__ wb2) {
    int i = blockIdx.x * blockDim.x + threadIdx.x;
    if (i < 192 * 128) {
        int n = i >> 7, k = i & 127;
        const float* w = (n < 64) ? w10 : ((n < 128) ? w11 : w12);
        wb1[i] = __float2half(w[k * 64 + (n & 63)]);
    }
    int j = i - 192 * 128;
    if (j >= 0 && j < 192 * 64) {
        int n = j >> 6, k = j & 63;
        const float* w = (n < 64) ? w20 : ((n < 128) ? w21 : w22);
        wb2[j] = __float2half(w[k * 64 + (n & 63)]);
    }
}

// ---------------- CSR build (concatenated) ------------------------------------
__global__ void k_zero(int* __restrict__ p, int n) {
    int i = blockIdx.x * blockDim.x + threadIdx.x;
    if (i < n) p[i] = 0;
}

__global__ void k_hist2(const int* __restrict__ dst1, const int* __restrict__ dst2,
                        int* __restrict__ deg, int E) {
    int e = blockIdx.x * blockDim.x + threadIdx.x;
    if (e < E)          atomicAdd(&deg[__ldcs(&dst1[e])], 1);
    else if (e < 2 * E) atomicAdd(&deg[N_NODES + __ldcs(&dst2[e - E])], 1);
}

__global__ void k_scan_sums(const int* __restrict__ deg, int* __restrict__ bsum, int n) {
    __shared__ int sh[16];
    int tid = threadIdx.x;
    int base = blockIdx.x * 2048 + tid * 4;
    int s = 0;
#pragma unroll
    for (int c = 0; c < 4; ++c) if (base + c < n) s += deg[base + c];
#pragma unroll
    for (int o = 16; o; o >>= 1) s += __shfl_xor_sync(0xffffffffu, s, o);
    if ((tid & 31) == 0) sh[tid >> 5] = s;
    __syncthreads();
    if (tid < 16) {
        int v = sh[tid];
#pragma unroll
        for (int o = 8; o; o >>= 1) v += __shfl_xor_sync(0x0000ffffu, v, o);
        if (tid == 0) bsum[blockIdx.x] = v;
    }
}

__global__ void k_scan_bsum(int* __restrict__ bsum, int nb) {
    __shared__ int ws[8];
    int tid = threadIdx.x;
    int lane = tid & 31, w = tid >> 5;
    int orig = (tid < nb) ? bsum[tid] : 0;
    int v = orig;
#pragma unroll
    for (int o = 1; o < 32; o <<= 1) {
        int t = __shfl_up_sync(0xffffffffu, v, o);
        if (lane >= o) v += t;
    }
    if (lane == 31) ws[w] = v;
    __syncthreads();
    if (tid == 0) { int a = 0; for (int i = 0; i < 8; ++i) { int t = ws[i]; ws[i] = a; a += t; } }
    __syncthreads();
    v += ws[w];
    if (tid < nb) bsum[tid] = v - orig;
}

__global__ void k_scan_write(int* __restrict__ deg, const int* __restrict__ bsum,
                             int* __restrict__ rs, int n, int total) {
    __shared__ int wsum[16];
    int tid = threadIdx.x;
    int lane = tid & 31, wid = tid >> 5;
    int base = blockIdx.x * 2048 + tid * 4;
    int v[4]; int s = 0;
#pragma unroll
    for (int c = 0; c < 4; ++c) { v[c] = (base + c < n) ? deg[base + c] : 0; s += v[c]; }
    int si = s;
#pragma unroll
    for (int o = 1; o < 32; o <<= 1) {
        int t = __shfl_up_sync(0xffffffffu, si, o);
        if (lane >= o) si += t;
    }
    if (lane == 31) wsum[wid] = si;
    __syncthreads();
    if (tid < 16) {
        int t = wsum[tid];
#pragma unroll
        for (int o = 1; o < 16; o <<= 1) {
            int u = __shfl_up_sync(0x0000ffffu, t, o);
            if (tid >= o) t += u;
        }
        wsum[tid] = t;
    }
    __syncthreads();
    int bbase = (wid == 0) ? 0 : wsum[wid - 1];
    int off = bsum[blockIdx.x] + bbase + (si - s);
#pragma unroll
    for (int c = 0; c < 4; ++c) {
        if (base + c < n) { rs[base + c] = off; deg[base + c] = off; off += v[c]; }
    }
    if (blockIdx.x == 0 && tid == 0) rs[n] = total;
}

__global__ void k_fill2(const int* __restrict__ src1, const int* __restrict__ dst1,
                        const float* __restrict__ w1,
                        const int* __restrict__ src2, const int* __restrict__ dst2,
                        const float* __restrict__ w2,
                        int* __restrict__ cur, int2* __restrict__ out, int E) {
    int e = blockIdx.x * blockDim.x + threadIdx.x;
    int s, slot; float w;
    if (e < E) {
        slot = __ldcs(&dst1[e]); s = __ldcs(&src1[e]); w = __ldcs(&w1[e]);
    } else if (e < 2 * E) {
        int e2 = e - E;
        slot = N_NODES + __ldcs(&dst2[e2]); s = __ldcs(&src2[e2]); w = __ldcs(&w2[e2]);
    } else return;
    int pos = atomicAdd(&cur[slot], 1);
    out[pos] = make_int2(s, __float_as_int(w));
}

// ---------------- HMMA GEMM: [M x K] @ [K x 192] -----------------------------
// A fp16 [128][K] row-major smem (padded), B fp16 [192][K] ("col-major" for mma).
// 16 warps 4(m) x 4(n); warp tile 32 x 48 = 2 x 6 m16n8k16 atoms.
template <int K>
__global__ void __launch_bounds__(512, 1)
k_gemm_mma(const float* __restrict__ X, const __half* __restrict__ WB,
           const float* __restrict__ B0, const float* __restrict__ B1,
           const float* __restrict__ B2,
           float* __restrict__ Y0, __half* __restrict__ Y1h,
           __half* __restrict__ Y2h, int M)
{
    constexpr int LDA = K + 8;                 // fp16 units; 16B pad -> no conflicts
    extern __shared__ __half sm[];
    __half* As = sm;                           // [128][LDA]
    __half* Bs = sm + 128 * LDA;               // [192][LDA]
    float*  cb = reinterpret_cast<float*>(Bs + 192 * LDA);   // [64]

    const int tid = threadIdx.x;
    const int r0  = blockIdx.x * 128;

    if (tid < 64) cb[tid] = B0[tid] + B1[tid] + B2[tid];

    // A: X fp32 -> fp16 (zero-fill rows >= M)
#pragma unroll
    for (int p = 0; p < (128 * K / 4) / 512; ++p) {
        int idx = p * 512 + tid;
        int m = idx / (K / 4), kq = idx % (K / 4), k = kq * 4;
        float4 v = make_float4(0.f, 0.f, 0.f, 0.f);
        if (r0 + m < M)
            v = __ldcs(reinterpret_cast<const float4*>(&X[(size_t)(r0 + m) * K + k]));
        __half2 h0 = __floats2half2_rn(v.x, v.y);
        __half2 h1 = __floats2half2_rn(v.z, v.w);
        uint2 st;
        st.x = *reinterpret_cast<uint32_t*>(&h0);
        st.y = *reinterpret_cast<uint32_t*>(&h1);
        *reinterpret_cast<uint2*>(&As[m * LDA + k]) = st;
    }
    // B: fp16 [n][k]
#pragma unroll
    for (int p = 0; p < (192 * K / 8) / 512; ++p) {
        int idx = p * 512 + tid;
        int n = idx / (K / 8), kq = idx % (K / 8), k = kq * 8;
        *reinterpret_cast<uint4*>(&Bs[n * LDA + k]) =
            *reinterpret_cast<const uint4*>(&WB[n * K + k]);
    }
    __syncthreads();

    const int warp = tid >> 5, lane = tid & 31;
    const int wm = warp & 3, wn = warp >> 2;   // 4 x 4
    const int m0 = wm * 32, n0 = wn * 48;

    float acc[2][6][4];
#pragma unroll
    for (int i = 0; i < 2; ++i)
#pragma unroll
        for (int j = 0; j < 6; ++j)
#pragma unroll
            for (int q = 0; q < 4; ++q) acc[i][j][q] = 0.f;

#pragma unroll
    for (int k0 = 0; k0 < K; k0 += 16) {
        uint32_t a[2][4];
#pragma unroll
        for (int ma = 0; ma < 2; ++ma) {
            uint32_t addr = smem_u32(
                &As[(m0 + ma * 16 + (lane & 15)) * LDA + k0 + (lane >> 4) * 8]);
            ldmatrix_x4(a[ma], addr);
        }
        uint32_t b[6][2];
#pragma unroll
        for (int nb = 0; nb < 6; ++nb) {
            uint32_t addr = smem_u32(
                &Bs[(n0 + nb * 8 + (lane & 7)) * LDA + k0 + ((lane >> 3) & 1) * 8]);
            ldmatrix_x2(b[nb], addr);
        }
#pragma unroll
        for (int ma = 0; ma < 2; ++ma)
#pragma unroll
            for (int nb = 0; nb < 6; ++nb)
                mma16816(acc[ma][nb], a[ma], b[nb]);
    }

    // epilogue: c0,c1 -> row lane/4; c2,c3 -> row lane/4+8; cols (lane&3)*2, +1
#pragma unroll
    for (int ma = 0; ma < 2; ++ma) {
#pragma unroll
        for (int h = 0; h < 2; ++h) {
            int row = r0 + m0 + ma * 16 + (lane >> 2) + h * 8;
            if (row >= M) continue;
#pragma unroll
            for (int nb = 0; nb < 6; ++nb) {
                float f0 = acc[ma][nb][h * 2];
                float f1 = acc[ma][nb][h * 2 + 1];
                int col = n0 + nb * 8 + (lane & 3) * 2;
                if (col < 64) {
                    float2 o = make_float2(f0 + cb[col], f1 + cb[col + 1]);
                    __stcs(reinterpret_cast<float2*>(&Y0[(size_t)row * 64 + col]), o);
                } else if (col < 128) {
                    *reinterpret_cast<__half2*>(&Y1h[(size_t)row * 64 + col - 64]) =
                        __floats2half2_rn(f0, f1);
                } else {
                    *reinterpret_cast<__half2*>(&Y2h[(size_t)row * 64 + col - 128]) =
                        __floats2half2_rn(f0, f1);
                }
            }
        }
    }
}

// ---------------- conv64 (R3 form, concat CSR) --------------------------------
__device__ __forceinline__ void conv_seg2(const __half* __restrict__ yt,
                                          const int* __restrict__ rs,
                                          const int2* __restrict__ ee,
                                          int nidx, int half, int sub, int lane,
                                          float4& acc)
{
    int p = __ldg(&rs[nidx]), pe = __ldg(&rs[nidx + 1]);
    while (p < pe) {
        int m = pe - p;
        int cnt = (m < 32) ? m : 32;
        int2 e = (lane < m) ? __ldcs(&ee[p + lane]) : make_int2(0, 0);
#pragma unroll 2
        for (int j = 0; j < cnt; j += 2) {
            int idx = j + half;
            int v = (idx < cnt);
            int sel = v ? idx : j;
            int   s = __shfl_sync(0xffffffffu, e.x, sel);
            float w = __int_as_float(__shfl_sync(0xffffffffu, e.y, sel));
            if (!v) w = 0.f;
            uint2 h = *reinterpret_cast<const uint2*>(yt + (size_t)s * 64 + sub * 4);
            float2 f0 = __half22float2(*reinterpret_cast<const __half2*>(&h.x));
            float2 f1 = __half22float2(*reinterpret_cast<const __half2*>(&h.y));
            acc.x = fmaf(w, f0.x, acc.x);
            acc.y = fmaf(w, f0.y, acc.y);
            acc.z = fmaf(w, f1.x, acc.z);
            acc.w = fmaf(w, f1.y, acc.w);
        }
        p += cnt;
    }
}

__global__ void k_conv64(const float* __restrict__ y0,
                         const __half* __restrict__ y1, const __half* __restrict__ y2,
                         const int* __restrict__ rs, const int2* __restrict__ ee,
                         float* __restrict__ xout, int M)
{
    int n = (blockIdx.x * blockDim.x + threadIdx.x) >> 5;
    if (n >= M) return;
    int lane = threadIdx.x & 31;
    int half = lane >> 4, sub = lane & 15;

    float4 acc = make_float4(0.f, 0.f, 0.f, 0.f);
    if (half == 0)
        acc = __ldcs(reinterpret_cast<const float4*>(&y0[(size_t)n * 64 + sub * 4]));

    conv_seg2(y1, rs, ee, n, half, sub, lane, acc);
    conv_seg2(y2, rs, ee, N_NODES + n, half, sub, lane, acc);

    acc.x += __shfl_xor_sync(0xffffffffu, acc.x, 16);
    acc.y += __shfl_xor_sync(0xffffffffu, acc.y, 16);
    acc.z += __shfl_xor_sync(0xffffffffu, acc.z, 16);
    acc.w += __shfl_xor_sync(0xffffffffu, acc.w, 16);
    if (half == 0)
        __stcs(reinterpret_cast<float4*>(&xout[(size_t)n * 64 + sub * 4]), acc);
}

// ---------------- block3 GEMM (64 -> 3 scalars): warp per node ---------------
__global__ void k_gemm3(const float* __restrict__ X,
                        const float* __restrict__ w0, const float* __restrict__ w1,
                        const float* __restrict__ w2,
                        const float* __restrict__ b0, const float* __restrict__ b1,
                        const float* __restrict__ b2,
                        float* __restrict__ s0, float* __restrict__ s1,
                        float* __restrict__ s2, int M)
{
    __shared__ float ws[3][64];
    int tid = threadIdx.x;
    if (tid < 64) { ws[0][tid] = w0[tid]; ws[1][tid] = w1[tid]; ws[2][tid] = w2[tid]; }
    __syncthreads();
    int n = blockIdx.x * (blockDim.x >> 5) + (tid >> 5);
    if (n >= M) return;
    int lane = tid & 31;
    float2 xv = __ldcs(reinterpret_cast<const float2*>(&X[(size_t)n * 64 + lane * 2]));
    float p0 = xv.x * ws[0][2 * lane] + xv.y * ws[0][2 * lane + 1];
    float p1 = xv.x * ws[1][2 * lane] + xv.y * ws[1][2 * lane + 1];
    float p2 = xv.x * ws[2][2 * lane] + xv.y * ws[2][2 * lane + 1];
#pragma unroll
    for (int o = 16; o; o >>= 1) {
        p0 += __shfl_xor_sync(0xffffffffu, p0, o);
        p1 += __shfl_xor_sync(0xffffffffu, p1, o);
        p2 += __shfl_xor_sync(0xffffffffu, p2, o);
    }
    if (lane == 0) {
        s0[n] = p0 + (b0[0] + b1[0] + b2[0]);
        s1[n] = p1;
        s2[n] = p2;
    }
}

// ---------------- block3 conv: warp per node ---------------------------------
__global__ void k_conv1(const float* __restrict__ s0, const float* __restrict__ s1,
                        const float* __restrict__ s2,
                        const int* __restrict__ rs, const int2* __restrict__ ee,
                        float* __restrict__ x3, int M)
{
    int n = (blockIdx.x * blockDim.x + threadIdx.x) >> 5;
    if (n >= M) return;
    int lane = threadIdx.x & 31;
    float acc = 0.f;
    for (int p = __ldg(&rs[n]) + lane, pe = __ldg(&rs[n + 1]); p < pe; p += 32) {
        int2 a = __ldcs(&ee[p]);
        acc = fmaf(__int_as_float(a.y), __ldg(&s1[a.x]), acc);
    }
    for (int p = __ldg(&rs[N_NODES + n]) + lane, pe = __ldg(&rs[N_NODES + n + 1]); p < pe; p += 32) {
        int2 a = __ldcs(&ee[p]);
        acc = fmaf(__int_as_float(a.y), __ldg(&s2[a.x]), acc);
    }
#pragma unroll
    for (int o = 16; o; o >>= 1) acc += __shfl_xor_sync(0xffffffffu, acc, o);
    if (lane == 0) x3[n] = s0[n] + acc;
}

// ---------------- readout + output copy --------------------------------------
__global__ void k_readout(const float* __restrict__ x3, float* __restrict__ out,
                          int out_size)
{
    __shared__ float sh[256];
    int g = blockIdx.x;
    float m = -3.402823466e38f;
    for (int i = threadIdx.x; i < NPG; i += blockDim.x)
        m = fmaxf(m, x3[g * NPG + i]);
    sh[threadIdx.x] = m;
    __syncthreads();
    for (int s = 128; s; s >>= 1) {
        if (threadIdx.x < s) sh[threadIdx.x] = fmaxf(sh[threadIdx.x], sh[threadIdx.x + s]);
        __syncthreads();
    }
    if (threadIdx.x == 0 && g < out_size) out[g] = sh[0];
}

__global__ void k_copy_out(const float* __restrict__ x3, float* __restrict__ out,
                           int out_size)
{
    int i = blockIdx.x * blockDim.x + threadIdx.x;
    if (i >= N_NODES) return;
    float v = __ldg(&x3[i]);
    if (4 + i < out_size)            __stcs(&out[4 + i], v);
    if (4 + N_NODES + i < out_size)  __stcs(&out[4 + N_NODES + i], v);
}

// ---------------------------------------------------------------------------
extern "C" void kernel_launch(void* const* d_in, const int* in_sizes, int n_in,
                              void* d_out, int out_size)
{
    const int E = N_EDGES, NN = N_NODES;

    const float* x   = (const float*)d_in[0];
    const int*   ei1 = (const int*)  d_in[1];
    const float* ew1 = (const float*)d_in[2];
    const int*   ei2 = (const int*)  d_in[3];
    const float* ew2 = (const float*)d_in[4];
    int base = (in_sizes[5] == 1) ? 6 : 5;
    const float* W[3][3]; const float* B[3][3];
    for (int blk = 0; blk < 3; ++blk)
        for (int part = 0; part < 3; ++part) {
            W[blk][part] = (const float*)d_in[base + blk * 6 + part * 2];
            B[blk][part] = (const float*)d_in[base + blk * 6 + part * 2 + 1];
        }

    float *y0, *gx, *s0, *s1, *s2, *x3;
    __half *y1h, *y2h, *wb1, *wb2;
    int *deg, *rs, *bs;
    int2 *ee;
    cudaGetSymbolAddress((void**)&y0, g_y0);
    cudaGetSymbolAddress((void**)&y1h, g_y1h);
    cudaGetSymbolAddress((void**)&y2h, g_y2h);
    cudaGetSymbolAddress((void**)&gx, g_x);
    cudaGetSymbolAddress((void**)&wb1, g_wb1h);
    cudaGetSymbolAddress((void**)&wb2, g_wb2h);
    cudaGetSymbolAddress((void**)&s0, g_s0);
    cudaGetSymbolAddress((void**)&s1, g_s1);
    cudaGetSymbolAddress((void**)&s2, g_s2);
    cudaGetSymbolAddress((void**)&x3, g_x3);
    cudaGetSymbolAddress((void**)&deg, g_deg);
    cudaGetSymbolAddress((void**)&rs, g_rs);
    cudaGetSymbolAddress((void**)&bs, g_bsum);
    cudaGetSymbolAddress((void**)&ee, g_e);

    static cudaStream_t sA = nullptr;
    static cudaEvent_t evRoot, evA, evX3, evCopy;
    if (!sA) {
        cudaStreamCreateWithFlags(&sA, cudaStreamNonBlocking);
        cudaEventCreateWithFlags(&evRoot, cudaEventDisableTiming);
        cudaEventCreateWithFlags(&evA,    cudaEventDisableTiming);
        cudaEventCreateWithFlags(&evX3,   cudaEventDisableTiming);
        cudaEventCreateWithFlags(&evCopy, cudaEventDisableTiming);
    }

    // smem: (128+192)*(K+8)*2 + 256
    const int smemG128 = 320 * 136 * 2 + 256;   // 87296
    const int smemG64  = 320 * 72 * 2 + 256;    // 46336
    cudaFuncSetAttribute(k_gemm_mma<128>, cudaFuncAttributeMaxDynamicSharedMemorySize, smemG128);
    cudaFuncSetAttribute(k_gemm_mma<64>,  cudaFuncAttributeMaxDynamicSharedMemorySize, smemG64);

    const int N2  = 2 * NN;
    const int SB  = (N2 + 2047) / 2048;
    const int EG2 = (2 * E + 255) / 256;
    const int NG2 = (N2 + 255) / 256;
    const int NG  = (NN + 255) / 256;
    const int GG  = (NN + 127) / 128;
    const int CG  = (NN * 32 + 255) / 256;

    // enqueue #1: weight prep (main; GEMM1 depends on it)
    k_prepw<<<144, 256>>>(W[0][0], W[0][1], W[0][2],
                          W[1][0], W[1][1], W[1][2], wb1, wb2);

    // fork CSR to side stream
    cudaEventRecord(evRoot, 0);
    cudaStreamWaitEvent(sA, evRoot, 0);

    k_zero<<<NG2, 256, 0, sA>>>(deg, N2);                    // #2
    k_hist2<<<EG2, 256, 0, sA>>>(ei1 + E, ei2 + E, deg, E);  // #3
    // enqueue #4: GEMM1 (the slot ncu captures)
    k_gemm_mma<128><<<GG, 512, smemG128>>>(x, wb1, B[0][0], B[0][1], B[0][2],
                                           y0, y1h, y2h, NN);
    k_scan_sums<<<SB, 512, 0, sA>>>(deg, bs, N2);
    k_scan_bsum<<<1, 256, 0, sA>>>(bs, SB);
    k_scan_write<<<SB, 512, 0, sA>>>(deg, bs, rs, N2, 2 * E);
    k_fill2<<<EG2, 256, 0, sA>>>(ei1, ei1 + E, ew1, ei2, ei2 + E, ew2, deg, ee, E);
    cudaEventRecord(evA, sA);

    // join
    cudaStreamWaitEvent(0, evA, 0);

    k_conv64<<<CG, 256>>>(y0, y1h, y2h, rs, ee, gx, NN);

    k_gemm_mma<64><<<GG, 512, smemG64>>>(gx, wb2, B[1][0], B[1][1], B[1][2],
                                         y0, y1h, y2h, NN);
    k_conv64<<<CG, 256>>>(y0, y1h, y2h, rs, ee, gx, NN);

    k_gemm3<<<CG, 256>>>(gx, W[2][0], W[2][1], W[2][2],
                         B[2][0], B[2][1], B[2][2], s0, s1, s2, NN);
    k_conv1<<<CG, 256>>>(s0, s1, s2, rs, ee, x3, NN);

    cudaEventRecord(evX3, 0);
    cudaStreamWaitEvent(sA, evX3, 0);
    k_copy_out<<<NG, 256, 0, sA>>>(x3, (float*)d_out, out_size);
    cudaEventRecord(evCopy, sA);

    k_readout<<<NGRAPH, 256>>>(x3, (float*)d_out, out_size);
    cudaStreamWaitEvent(0, evCopy, 0);
}